// round 5
// baseline (speedup 1.0000x reference)
#include <cuda_runtime.h>

// SphereConv R5: cp.async (LDGSTS) smem pipeline.
// Block = (b, l): 128 threads, all 8 f, all 256 m (2 m/thread -> 16 u64 accums).
// x staged into a 3-deep smem ring in chunks of 4 c (8 KB/chunk) with
// cp.async.cg; compute reads smem only (29-cyc LDS), so DRAM latency is
// hidden by pipeline depth x 7 CTAs/SM. x read ONCE (84 MB total DRAM).

#define B_ 4
#define C_ 32
#define L_ 256
#define M_ 256
#define F_ 8
#define N_ 64
#define CH 4                 // c's per chunk
#define DEPTH 3              // ring depth
#define NCH (C_ / CH)        // 8 chunks

typedef unsigned long long u64;
typedef unsigned int u32;

__device__ __forceinline__ u64 pk2(float lo, float hi) {
    u64 r;
    asm("mov.b64 %0, {%1, %2};" : "=l"(r) : "f"(lo), "f"(hi));
    return r;
}
__device__ __forceinline__ void upk2(u64 v, float& lo, float& hi) {
    asm("mov.b64 {%0, %1}, %2;" : "=f"(lo), "=f"(hi) : "l"(v));
}
__device__ __forceinline__ u64 ffma2(u64 a, u64 b, u64 c) {
    u64 d;
    asm("fma.rn.f32x2 %0, %1, %2, %3;" : "=l"(d) : "l"(a), "l"(b), "l"(c));
    return d;
}
__device__ __forceinline__ void cp16(u32 dst, const float* src) {
    asm volatile("cp.async.cg.shared.global [%0], [%1], 16;" :: "r"(dst), "l"(src));
}
__device__ __forceinline__ void cp_commit() {
    asm volatile("cp.async.commit_group;");
}

__global__ void __launch_bounds__(128, 7) sphere_conv_kernel(
    const float* __restrict__ xr, const float* __restrict__ xi,
    const float* __restrict__ wr, const float* __restrict__ wi,
    float* __restrict__ out)
{
    __shared__ __align__(16) float xbuf[DEPTH][CH][2][M_];   // 24 KB ring
    __shared__ __align__(16) u64 swr[C_ * F_];               // {s*wr, s*wr}
    __shared__ __align__(16) u64 swi[C_ * F_];               // {s*wi, s*wi}
    __shared__ __align__(16) u64 snw[C_ * F_];               // {-s*wi,-s*wi}

    const int b   = blockIdx.x;     // 0..3
    const int l   = blockIdx.y;     // 0..255
    const int tid = threadIdx.x;    // 0..127

    // --- weight interpolation: 256 (f,c) pairs, 2 per thread ---
    {
        float t = ((float)l / (float)(L_ - 1)) * (float)(N_ - 1);
        int lo = (int)floorf(t);
        lo = lo < 0 ? 0 : (lo > N_ - 2 ? N_ - 2 : lo);
        const float fr = t - (float)lo;
        const float s  = sqrtf(1.0f + (float)l) * (1.0f / (float)C_);
        #pragma unroll
        for (int k = 0; k < 2; ++k) {
            const int idx = tid + k * 128;        // (f,c) flat: f = idx>>5, c = idx&31
            const int f = idx >> 5, c = idx & 31;
            const int base = (f * C_ + c) * N_ + lo;
            float wrv = wr[base] * (1.0f - fr) + wr[base + 1] * fr;
            float wiv = wi[base] * (1.0f - fr) + wi[base + 1] * fr;
            wrv *= s; wiv *= s;
            swr[c * F_ + f] = pk2(wrv, wrv);
            swi[c * F_ + f] = pk2(wiv, wiv);
            snw[c * F_ + f] = pk2(-wiv, -wiv);
        }
    }

    // --- staging geometry: 8 rows/chunk (4 c x {r,i}), each row 1 KB ---
    const int row  = tid >> 4;          // 0..7
    const int ci   = row >> 1;          // local c 0..3
    const int part = row & 1;           // 0=real, 1=imag
    const int slot = tid & 15;          // 16B slot
    const float* gsrc0 = (part ? xi : xr)
                       + ((u64)(b * C_ + ci) * L_ + l) * M_ + slot * 4;
    const u32 sdst0 = (u32)__cvta_generic_to_shared(&xbuf[0][ci][part][slot * 4]);
    const u32 bufStride = (u32)(sizeof(float) * CH * 2 * M_);  // 8 KB

    auto stage = [&](int chunk) {
        const float* s = gsrc0 + (u64)(chunk * CH) * (L_ * M_);
        const u32 d = sdst0 + (u32)(chunk % DEPTH) * bufStride;
        #pragma unroll
        for (int j = 0; j < 4; ++j) cp16(d + j * 256u, s + j * 64);
        cp_commit();
    };

    stage(0);
    stage(1);

    const int m0 = tid << 1;            // 2 m per thread

    u64 aR[F_], aI[F_];
    #pragma unroll
    for (int f = 0; f < F_; ++f) { aR[f] = 0ull; aI[f] = 0ull; }

    #pragma unroll 1
    for (int k = 0; k < NCH; ++k) {
        if (k < NCH - 2) {
            asm volatile("cp.async.wait_group 1;");
        } else {
            asm volatile("cp.async.wait_group 0;");
        }
        __syncthreads();
        if (k + 2 < NCH) stage(k + 2);   // into buf (k-1)%DEPTH, freed by sync

        const int bufi = k % DEPTH;
        #pragma unroll
        for (int cc = 0; cc < CH; ++cc) {
            const int c = k * CH + cc;
            const u64 x_r = *(const u64*)&xbuf[bufi][cc][0][m0];
            const u64 x_i = *(const u64*)&xbuf[bufi][cc][1][m0];
            const ulonglong2* __restrict__ pwr = (const ulonglong2*)(swr + c * F_);
            const ulonglong2* __restrict__ pwi = (const ulonglong2*)(swi + c * F_);
            const ulonglong2* __restrict__ pnw = (const ulonglong2*)(snw + c * F_);
            #pragma unroll
            for (int fp = 0; fp < F_ / 2; ++fp) {
                const ulonglong2 w_r = pwr[fp];
                const ulonglong2 w_i = pwi[fp];
                const ulonglong2 w_n = pnw[fp];
                const int f0 = fp * 2;
                aR[f0]   = ffma2(w_r.x, x_r, aR[f0]);
                aR[f0]   = ffma2(w_n.x, x_i, aR[f0]);
                aI[f0]   = ffma2(w_r.x, x_i, aI[f0]);
                aI[f0]   = ffma2(w_i.x, x_r, aI[f0]);
                aR[f0+1] = ffma2(w_r.y, x_r, aR[f0+1]);
                aR[f0+1] = ffma2(w_n.y, x_i, aR[f0+1]);
                aI[f0+1] = ffma2(w_r.y, x_i, aI[f0+1]);
                aI[f0+1] = ffma2(w_i.y, x_r, aI[f0+1]);
            }
        }
    }

    // --- epilogue: relu on real only, write (2, B, F, L, M) ---
    const int outHalf = B_ * F_ * L_ * M_;
    #pragma unroll
    for (int f = 0; f < F_; ++f) {
        const int oR = ((b * F_ + f) * L_ + l) * M_ + m0;
        float r0, r1, i0, i1;
        upk2(aR[f], r0, r1);
        upk2(aI[f], i0, i1);
        *(float2*)(out + oR)           = make_float2(fmaxf(r0, 0.0f), fmaxf(r1, 0.0f));
        *(float2*)(out + outHalf + oR) = make_float2(i0, i1);
    }
}

extern "C" void kernel_launch(void* const* d_in, const int* in_sizes, int n_in,
                              void* d_out, int out_size) {
    const float* xr = (const float*)d_in[0];
    const float* xi = (const float*)d_in[1];
    const float* wr = (const float*)d_in[2];
    const float* wi = (const float*)d_in[3];
    float* out = (float*)d_out;
    dim3 grid(B_, L_);   // (b, l): 1024 blocks, 7 CTAs/SM, single wave
    sphere_conv_kernel<<<grid, 128>>>(xr, xi, wr, wi, out);
}